// round 3
// baseline (speedup 1.0000x reference)
#include <cuda_runtime.h>
#include <cuda_bf16.h>

#define N_NODES 50000
#define N_EDGES 800000
#define VOCABSZ 4096
#define EMB_DIM 128
#define H2 256      // 2*HIDDEN
#define HID 128
#define N_POS 1024
#define NBLK_NODES 196   // ceil(50000/256)

// ---------------- scratch (device globals) ----------------------------------
__device__ float d_EW[VOCABSZ * H2];        // emb @ W1, 4 MB (L2-resident)
__device__ float d_dinv[N_NODES];
__device__ int   d_deg[N_NODES];            // raw in-degree (no self loop)
__device__ int   d_cnt[N_NODES];            // multiplicity in x_position
__device__ float d_coef[N_NODES];           // layer-2 weight per needed node
__device__ unsigned char d_need[N_NODES];   // h1 needed at this node?
__device__ int   d_start[N_NODES];          // CSR start (unordered segments)
__device__ int   d_cursor[N_NODES];         // CSR fill cursor
__device__ int   d_list[N_NODES];           // compact list of needed nodes
__device__ int   d_nneed;
__device__ int   d_total;
__device__ int2  d_csr[N_EDGES];            // {x[row], bits(dinv[row]*dinv[col])}
__device__ float d_svec[H2];

__device__ __forceinline__ void red4(float4* p, float a, float b, float c, float d) {
    asm volatile("red.global.add.v4.f32 [%0], {%1,%2,%3,%4};"
                 :: "l"(p), "f"(a), "f"(b), "f"(c), "f"(d) : "memory");
}

// ---------------- K0: zero all counters in one launch -----------------------
__global__ void k_init() {
    int i = blockIdx.x * 256 + threadIdx.x;
    if (i < N_NODES) { d_deg[i] = 0; d_cnt[i] = 0; d_coef[i] = 0.f; d_need[i] = 0; }
    if (i < H2) d_svec[i] = 0.f;
    if (i == 0) { d_nneed = 0; d_total = 0; }
}

// ---------------- K1: EW = emb @ W1 -----------------------------------------
__global__ void k_ew(const float* __restrict__ emb, const float* __restrict__ W1) {
    __shared__ float se[16 * 128];
    int t0 = blockIdx.x * 16;
    for (int i = threadIdx.x; i < 16 * 128; i += 256) se[i] = emb[t0 * 128 + i];
    __syncthreads();
    int j = threadIdx.x;
    float acc[16];
#pragma unroll
    for (int r = 0; r < 16; r++) acc[r] = 0.f;
    for (int k = 0; k < 128; k++) {
        float w = W1[k * H2 + j];
#pragma unroll
        for (int r = 0; r < 16; r++) acc[r] += se[r * 128 + k] * w;
    }
#pragma unroll
    for (int r = 0; r < 16; r++) d_EW[(t0 + r) * H2 + j] = acc[r];
}

// ---------------- K2: degree + selected-count (int4 vectorized) -------------
__global__ void k_deg(const int* __restrict__ col, const int* __restrict__ pos) {
    int i4 = blockIdx.x * blockDim.x + threadIdx.x;
    if (i4 < N_EDGES / 4) {
        int4 c = ((const int4*)col)[i4];
        atomicAdd(&d_deg[c.x], 1);
        atomicAdd(&d_deg[c.y], 1);
        atomicAdd(&d_deg[c.z], 1);
        atomicAdd(&d_deg[c.w], 1);
    }
    if (i4 < N_POS) atomicAdd(&d_cnt[pos[i4]], 1);
}

// ---------------- K3: dinv + need flags from positions ----------------------
__global__ void k_dinv(const int* __restrict__ pos) {
    int v = blockIdx.x * blockDim.x + threadIdx.x;
    if (v < N_NODES) d_dinv[v] = rsqrtf((float)d_deg[v] + 1.0f);
    if (v < N_POS) d_need[pos[v]] = 1;
}

// ---------------- K4: per-source coef + need flags (int4) -------------------
__global__ void k_coef(const int* __restrict__ row, const int* __restrict__ col) {
    int i4 = blockIdx.x * blockDim.x + threadIdx.x;
    if (i4 >= N_EDGES / 4) return;
    int4 c = ((const int4*)col)[i4];
    int4 r = ((const int4*)row)[i4];
    int k;
#define DO_E(rr, cc) \
    k = d_cnt[cc]; \
    if (k > 0) { \
        atomicAdd(&d_coef[rr], d_dinv[rr] * d_dinv[cc] * (float)k); \
        d_need[rr] = 1; \
    }
    DO_E(r.x, c.x) DO_E(r.y, c.y) DO_E(r.z, c.z) DO_E(r.w, c.w)
#undef DO_E
}

// ---------------- K5: unordered CSR range allocation (replaces 3-kernel scan)
__global__ void k_alloc() {
    int u = blockIdx.x * 256 + threadIdx.x;
    if (u >= N_NODES || !d_need[u]) return;
    int st = atomicAdd(&d_total, d_deg[u]);
    d_start[u] = st;
    d_cursor[u] = st;
    int li = atomicAdd(&d_nneed, 1);
    d_list[li] = u;
}

// ---------------- K6: CSR build (int4) --------------------------------------
__global__ void k_csr(const int* __restrict__ row, const int* __restrict__ col,
                      const int* __restrict__ x) {
    int i4 = blockIdx.x * blockDim.x + threadIdx.x;
    if (i4 >= N_EDGES / 4) return;
    int4 c = ((const int4*)col)[i4];
    int4 r = ((const int4*)row)[i4];
#define DO_E(rr, cc) \
    if (d_need[cc]) { \
        int idx = atomicAdd(&d_cursor[cc], 1); \
        float w = d_dinv[rr] * d_dinv[cc]; \
        d_csr[idx] = make_int2(x[rr], __float_as_int(w)); \
    }
    DO_E(r.x, c.x) DO_E(r.y, c.y) DO_E(r.z, c.z) DO_E(r.w, c.w)
#undef DO_E
}

// ---------------- K7: fused gather: h1 + relu + layer-2 reduction -----------
// warp-per-node; inner loop processes 4 edges per iteration (8 LDG.128 in flight)
__global__ void k_gather(const float* __restrict__ b1, const int* __restrict__ x) {
    __shared__ float ssv[H2];
    int tid = threadIdx.x;
    ssv[tid] = 0.f;
    __syncthreads();
    int lane = tid & 31;
    int gw = (blockIdx.x * blockDim.x + tid) >> 5;
    int nw = (gridDim.x * blockDim.x) >> 5;
    int nn = d_nneed;
    float4 bb0 = ((const float4*)b1)[lane];
    float4 bb1 = ((const float4*)b1)[lane + 32];
    const float4* EW4 = (const float4*)d_EW;
    float4 sv0 = make_float4(0, 0, 0, 0), sv1 = make_float4(0, 0, 0, 0);
    for (int idx = gw; idx < nn; idx += nw) {
        int u = d_list[idx];
        float du = d_dinv[u];
        float d2 = du * du;
        const float4* su = EW4 + (size_t)x[u] * 64;
        float4 a0 = su[lane], a1 = su[lane + 32];
        a0.x *= d2; a0.y *= d2; a0.z *= d2; a0.w *= d2;
        a1.x *= d2; a1.y *= d2; a1.z *= d2; a1.w *= d2;
        int s0 = d_start[u], len = d_deg[u];
        for (int b = 0; b < len; b += 32) {
            int i = b + lane;
            int2 ev = (i < len) ? d_csr[s0 + i] : make_int2(0, 0);
            float wl = (i < len) ? __int_as_float(ev.y) : 0.f;
            int n = min(32, len - b);
            int n4 = (n + 3) & ~3;
            for (int j = 0; j < n4; j += 4) {
                int x0 = __shfl_sync(0xffffffffu, ev.x, j + 0);
                int x1 = __shfl_sync(0xffffffffu, ev.x, j + 1);
                int x2 = __shfl_sync(0xffffffffu, ev.x, j + 2);
                int x3 = __shfl_sync(0xffffffffu, ev.x, j + 3);
                float w0 = __shfl_sync(0xffffffffu, wl, j + 0);
                float w1 = __shfl_sync(0xffffffffu, wl, j + 1);
                float w2 = __shfl_sync(0xffffffffu, wl, j + 2);
                float w3 = __shfl_sync(0xffffffffu, wl, j + 3);
                const float4* p0 = EW4 + (size_t)x0 * 64;
                const float4* p1 = EW4 + (size_t)x1 * 64;
                const float4* p2 = EW4 + (size_t)x2 * 64;
                const float4* p3 = EW4 + (size_t)x3 * 64;
                float4 u00 = p0[lane], u01 = p0[lane + 32];
                float4 u10 = p1[lane], u11 = p1[lane + 32];
                float4 u20 = p2[lane], u21 = p2[lane + 32];
                float4 u30 = p3[lane], u31 = p3[lane + 32];
                a0.x += w0 * u00.x; a0.y += w0 * u00.y; a0.z += w0 * u00.z; a0.w += w0 * u00.w;
                a1.x += w0 * u01.x; a1.y += w0 * u01.y; a1.z += w0 * u01.z; a1.w += w0 * u01.w;
                a0.x += w1 * u10.x; a0.y += w1 * u10.y; a0.z += w1 * u10.z; a0.w += w1 * u10.w;
                a1.x += w1 * u11.x; a1.y += w1 * u11.y; a1.z += w1 * u11.z; a1.w += w1 * u11.w;
                a0.x += w2 * u20.x; a0.y += w2 * u20.y; a0.z += w2 * u20.z; a0.w += w2 * u20.w;
                a1.x += w2 * u21.x; a1.y += w2 * u21.y; a1.z += w2 * u21.z; a1.w += w2 * u21.w;
                a0.x += w3 * u30.x; a0.y += w3 * u30.y; a0.z += w3 * u30.z; a0.w += w3 * u30.w;
                a1.x += w3 * u31.x; a1.y += w3 * u31.y; a1.z += w3 * u31.z; a1.w += w3 * u31.w;
            }
        }
        float ct = d_coef[u] + (float)d_cnt[u] * d2;
        sv0.x += ct * fmaxf(a0.x + bb0.x, 0.f);
        sv0.y += ct * fmaxf(a0.y + bb0.y, 0.f);
        sv0.z += ct * fmaxf(a0.z + bb0.z, 0.f);
        sv0.w += ct * fmaxf(a0.w + bb0.w, 0.f);
        sv1.x += ct * fmaxf(a1.x + bb1.x, 0.f);
        sv1.y += ct * fmaxf(a1.y + bb1.y, 0.f);
        sv1.z += ct * fmaxf(a1.z + bb1.z, 0.f);
        sv1.w += ct * fmaxf(a1.w + bb1.w, 0.f);
    }
    atomicAdd(&ssv[4 * lane + 0], sv0.x);
    atomicAdd(&ssv[4 * lane + 1], sv0.y);
    atomicAdd(&ssv[4 * lane + 2], sv0.z);
    atomicAdd(&ssv[4 * lane + 3], sv0.w);
    atomicAdd(&ssv[128 + 4 * lane + 0], sv1.x);
    atomicAdd(&ssv[128 + 4 * lane + 1], sv1.y);
    atomicAdd(&ssv[128 + 4 * lane + 2], sv1.z);
    atomicAdd(&ssv[128 + 4 * lane + 3], sv1.w);
    __syncthreads();
    if (tid < 64) {
        float4 p = ((float4*)ssv)[tid];
        red4(((float4*)d_svec) + tid, p.x, p.y, p.z, p.w);
    }
}

// ---------------- K8: fused zbar + classifier -------------------------------
__global__ void k_out(const float* __restrict__ W2, const float* __restrict__ b2,
                      const float* __restrict__ Wc, const float* __restrict__ bc,
                      float* __restrict__ out) {
    __shared__ float zb[HID];
    int t = threadIdx.x;
    if (t < HID) {
        float acc = 0.f;
        for (int k = 0; k < H2; k++) acc += d_svec[k] * W2[k * HID + t];
        zb[t] = acc * (1.0f / (float)N_POS) + b2[t];
    }
    __syncthreads();
    int c = blockIdx.x * 256 + t;
    float acc = bc[c];
#pragma unroll 8
    for (int j = 0; j < HID; j++) acc += zb[j] * Wc[j * VOCABSZ + c];
    out[c] = acc;
}

extern "C" void kernel_launch(void* const* d_in, const int* in_sizes, int n_in,
                              void* d_out, int out_size) {
    const int*   x    = (const int*)d_in[0];
    const int*   ei   = (const int*)d_in[1];
    const int*   pos  = (const int*)d_in[2];
    const float* emb  = (const float*)d_in[3];
    const float* W1   = (const float*)d_in[4];
    const float* b1   = (const float*)d_in[5];
    const float* W2   = (const float*)d_in[6];
    const float* b2   = (const float*)d_in[7];
    const float* Wc   = (const float*)d_in[8];
    const float* bc   = (const float*)d_in[9];
    float* out = (float*)d_out;
    const int* row = ei;
    const int* col = ei + N_EDGES;

    k_init<<<NBLK_NODES, 256>>>();
    k_ew<<<VOCABSZ / 16, 256>>>(emb, W1);
    k_deg<<<(N_EDGES / 4 + 255) / 256, 256>>>(col, pos);
    k_dinv<<<(N_NODES + 255) / 256, 256>>>(pos);
    k_coef<<<(N_EDGES / 4 + 255) / 256, 256>>>(row, col);
    k_alloc<<<NBLK_NODES, 256>>>();
    k_csr<<<(N_EDGES / 4 + 255) / 256, 256>>>(row, col, x);
    k_gather<<<2048, 256>>>(b1, x);
    k_out<<<VOCABSZ / 256, 256>>>(W2, b2, Wc, bc, out);
}

// round 5
// speedup vs baseline: 1.1395x; 1.1395x over previous
#include <cuda_runtime.h>
#include <cuda_bf16.h>

#define N_NODES 50000
#define N_EDGES 800000
#define VOCABSZ 4096
#define EMB_DIM 128
#define H2 256      // 2*HIDDEN
#define HID 128
#define N_POS 1024
#define NBLK_NODES 196   // ceil(50000/256)
#define EW_BLKS 256      // 4096/16

// ---------------- scratch (device globals) ----------------------------------
__device__ uint4 d_EWh[VOCABSZ * 32];       // emb @ W1 in bf16x2, 2 MB (L2-resident)
__device__ int   d_dc[2 * N_NODES];         // interleaved {deg, cnt} per node
__device__ float d_coef[N_NODES];           // layer-2 edge weight per source node
__device__ unsigned char d_need[N_NODES];   // h1 needed at this node?
__device__ int   d_start[N_NODES];          // CSR start (unordered segments)
__device__ int   d_cursor[N_NODES];         // CSR fill cursor
__device__ int   d_list[N_NODES];           // compact list of needed nodes
__device__ int   d_nneed;
__device__ int   d_total;
__device__ int2  d_csr[N_EDGES];            // {x[row], bits(dinv_r*dinv_c)}
__device__ float d_svec[H2];

__device__ __forceinline__ void red4(float4* p, float a, float b, float c, float d) {
    asm volatile("red.global.add.v4.f32 [%0], {%1,%2,%3,%4};"
                 :: "l"(p), "f"(a), "f"(b), "f"(c), "f"(d) : "memory");
}

// accumulate 8 bf16 values (packed in a uint4) scaled by w into a[8]
__device__ __forceinline__ void acc8(float* a, uint4 q, float w) {
    float2 f0 = __bfloat1622float2(*(const __nv_bfloat162*)&q.x);
    float2 f1 = __bfloat1622float2(*(const __nv_bfloat162*)&q.y);
    float2 f2 = __bfloat1622float2(*(const __nv_bfloat162*)&q.z);
    float2 f3 = __bfloat1622float2(*(const __nv_bfloat162*)&q.w);
    a[0] += w * f0.x; a[1] += w * f0.y;
    a[2] += w * f1.x; a[3] += w * f1.y;
    a[4] += w * f2.x; a[5] += w * f2.y;
    a[6] += w * f3.x; a[7] += w * f3.y;
}

// ---------------- K0: fused EW-GEMM (blocks 0..255) + zero (blocks 256..) ---
__global__ void k_prep(const float* __restrict__ emb, const float* __restrict__ W1) {
    if (blockIdx.x < EW_BLKS) {
        __shared__ float se[16 * 128];
        int t0 = blockIdx.x * 16;
        for (int i = threadIdx.x; i < 16 * 128; i += 256) se[i] = emb[t0 * 128 + i];
        __syncthreads();
        int j = threadIdx.x;   // output column 0..255
        float acc[16];
#pragma unroll
        for (int r = 0; r < 16; r++) acc[r] = 0.f;
        for (int k = 0; k < 128; k++) {
            float w = W1[k * H2 + j];
#pragma unroll
            for (int r = 0; r < 16; r++) acc[r] += se[r * 128 + k] * w;
        }
        unsigned* EWu = (unsigned*)d_EWh;
#pragma unroll
        for (int r = 0; r < 16; r++) {
            float v = acc[r];
            float vh = __shfl_down_sync(0xffffffffu, v, 1);
            if ((j & 1) == 0) {
                __nv_bfloat162 h = __floats2bfloat162_rn(v, vh);
                EWu[(t0 + r) * 128 + (j >> 1)] = *(unsigned*)&h;
            }
        }
    } else {
        int i = (blockIdx.x - EW_BLKS) * 256 + threadIdx.x;
        if (i < N_NODES) {
            d_dc[2 * i] = 0; d_dc[2 * i + 1] = 0;
            d_coef[i] = 0.f; d_need[i] = 0;
        }
        if (i < H2) d_svec[i] = 0.f;
        if (i == 0) { d_nneed = 0; d_total = 0; }
    }
}

// ---------------- K1: degree + selected-count + need[pos] -------------------
__global__ void k_deg(const int* __restrict__ col, const int* __restrict__ pos) {
    int i4 = blockIdx.x * blockDim.x + threadIdx.x;
    if (i4 < N_EDGES / 4) {
        int4 c = ((const int4*)col)[i4];
        atomicAdd(&d_dc[2 * c.x], 1);
        atomicAdd(&d_dc[2 * c.y], 1);
        atomicAdd(&d_dc[2 * c.z], 1);
        atomicAdd(&d_dc[2 * c.w], 1);
    }
    if (i4 < N_POS) {
        int p = pos[i4];
        atomicAdd(&d_dc[2 * p + 1], 1);
        d_need[p] = 1;
    }
}

// ---------------- K2: per-source coef + need flags (int4, on-the-fly dinv) --
__global__ void k_coef(const int* __restrict__ row, const int* __restrict__ col) {
    int i4 = blockIdx.x * blockDim.x + threadIdx.x;
    if (i4 >= N_EDGES / 4) return;
    int4 c = ((const int4*)col)[i4];
    int4 r = ((const int4*)row)[i4];
#define DO_E(rr, cc) { \
    int2 dcc = *(const int2*)&d_dc[2 * (cc)]; \
    if (dcc.y > 0) { \
        float w = rsqrtf((float)d_dc[2 * (rr)] + 1.f) * rsqrtf((float)dcc.x + 1.f) * (float)dcc.y; \
        atomicAdd(&d_coef[rr], w); \
        d_need[rr] = 1; \
    } }
    DO_E(r.x, c.x) DO_E(r.y, c.y) DO_E(r.z, c.z) DO_E(r.w, c.w)
#undef DO_E
}

// ---------------- K3: unordered CSR range allocation ------------------------
__global__ void k_alloc() {
    int u = blockIdx.x * 256 + threadIdx.x;
    if (u >= N_NODES || !d_need[u]) return;
    int st = atomicAdd(&d_total, d_dc[2 * u]);
    d_start[u] = st;
    d_cursor[u] = st;
    int li = atomicAdd(&d_nneed, 1);
    d_list[li] = u;
}

// ---------------- K4: CSR build (int4) --------------------------------------
__global__ void k_csr(const int* __restrict__ row, const int* __restrict__ col,
                      const int* __restrict__ x) {
    int i4 = blockIdx.x * blockDim.x + threadIdx.x;
    if (i4 >= N_EDGES / 4) return;
    int4 c = ((const int4*)col)[i4];
    int4 r = ((const int4*)row)[i4];
#define DO_E(rr, cc) \
    if (d_need[cc]) { \
        int idx = atomicAdd(&d_cursor[cc], 1); \
        float w = rsqrtf((float)d_dc[2 * (rr)] + 1.f) * rsqrtf((float)d_dc[2 * (cc)] + 1.f); \
        d_csr[idx] = make_int2(x[rr], __float_as_int(w)); \
    }
    DO_E(r.x, c.x) DO_E(r.y, c.y) DO_E(r.z, c.z) DO_E(r.w, c.w)
#undef DO_E
}

// ---------------- K5: fused gather (bf16 EW): h1 + relu + layer-2 reduction -
// warp-per-node; each lane owns output cols [8*lane, 8*lane+8)
__global__ void k_gather(const float* __restrict__ b1, const int* __restrict__ x) {
    __shared__ float ssv[H2];
    int tid = threadIdx.x;
    ssv[tid] = 0.f;
    __syncthreads();
    int lane = tid & 31;
    int gw = (blockIdx.x * blockDim.x + tid) >> 5;
    int nw = (gridDim.x * blockDim.x) >> 5;
    int nn = d_nneed;
    float4 bq0 = ((const float4*)b1)[2 * lane];
    float4 bq1 = ((const float4*)b1)[2 * lane + 1];
    float sv[8];
#pragma unroll
    for (int k = 0; k < 8; k++) sv[k] = 0.f;
    for (int idx = gw; idx < nn; idx += nw) {
        int u = d_list[idx];
        int2 dcu = *(const int2*)&d_dc[2 * u];
        float du = rsqrtf((float)dcu.x + 1.f);
        float d2 = du * du;
        int toku = x[u];
        float a[8];
#pragma unroll
        for (int k = 0; k < 8; k++) a[k] = 0.f;
        acc8(a, d_EWh[(size_t)toku * 32 + lane], d2);
        int s0 = d_start[u], len = dcu.x;
        for (int b = 0; b < len; b += 32) {
            int i = b + lane;
            int2 ev = (i < len) ? d_csr[s0 + i] : make_int2(0, 0);
            float wl = (i < len) ? __int_as_float(ev.y) : 0.f;
            int n4 = (min(32, len - b) + 3) & ~3;
            for (int j = 0; j < n4; j += 4) {
                int t0 = __shfl_sync(0xffffffffu, ev.x, j + 0);
                int t1 = __shfl_sync(0xffffffffu, ev.x, j + 1);
                int t2 = __shfl_sync(0xffffffffu, ev.x, j + 2);
                int t3 = __shfl_sync(0xffffffffu, ev.x, j + 3);
                float w0 = __shfl_sync(0xffffffffu, wl, j + 0);
                float w1 = __shfl_sync(0xffffffffu, wl, j + 1);
                float w2 = __shfl_sync(0xffffffffu, wl, j + 2);
                float w3 = __shfl_sync(0xffffffffu, wl, j + 3);
                uint4 q0 = d_EWh[(size_t)t0 * 32 + lane];
                uint4 q1 = d_EWh[(size_t)t1 * 32 + lane];
                uint4 q2 = d_EWh[(size_t)t2 * 32 + lane];
                uint4 q3 = d_EWh[(size_t)t3 * 32 + lane];
                acc8(a, q0, w0);
                acc8(a, q1, w1);
                acc8(a, q2, w2);
                acc8(a, q3, w3);
            }
        }
        float ct = d_coef[u] + (float)dcu.y * d2;
        sv[0] += ct * fmaxf(a[0] + bq0.x, 0.f);
        sv[1] += ct * fmaxf(a[1] + bq0.y, 0.f);
        sv[2] += ct * fmaxf(a[2] + bq0.z, 0.f);
        sv[3] += ct * fmaxf(a[3] + bq0.w, 0.f);
        sv[4] += ct * fmaxf(a[4] + bq1.x, 0.f);
        sv[5] += ct * fmaxf(a[5] + bq1.y, 0.f);
        sv[6] += ct * fmaxf(a[6] + bq1.z, 0.f);
        sv[7] += ct * fmaxf(a[7] + bq1.w, 0.f);
    }
#pragma unroll
    for (int k = 0; k < 8; k++) atomicAdd(&ssv[8 * lane + k], sv[k]);
    __syncthreads();
    if (tid < 64) {
        float4 p = ((float4*)ssv)[tid];
        red4(((float4*)d_svec) + tid, p.x, p.y, p.z, p.w);
    }
}

// ---------------- K6: fused zbar + classifier -------------------------------
__global__ void k_out(const float* __restrict__ W2, const float* __restrict__ b2,
                      const float* __restrict__ Wc, const float* __restrict__ bc,
                      float* __restrict__ out) {
    __shared__ float zb[HID];
    int t = threadIdx.x;
    if (t < HID) {
        float acc = 0.f;
        for (int k = 0; k < H2; k++) acc += d_svec[k] * W2[k * HID + t];
        zb[t] = acc * (1.0f / (float)N_POS) + b2[t];
    }
    __syncthreads();
    int c = blockIdx.x * 256 + t;
    float acc = bc[c];
#pragma unroll 8
    for (int j = 0; j < HID; j++) acc += zb[j] * Wc[j * VOCABSZ + c];
    out[c] = acc;
}

extern "C" void kernel_launch(void* const* d_in, const int* in_sizes, int n_in,
                              void* d_out, int out_size) {
    const int*   x    = (const int*)d_in[0];
    const int*   ei   = (const int*)d_in[1];
    const int*   pos  = (const int*)d_in[2];
    const float* emb  = (const float*)d_in[3];
    const float* W1   = (const float*)d_in[4];
    const float* b1   = (const float*)d_in[5];
    const float* W2   = (const float*)d_in[6];
    const float* b2   = (const float*)d_in[7];
    const float* Wc   = (const float*)d_in[8];
    const float* bc   = (const float*)d_in[9];
    float* out = (float*)d_out;
    const int* row = ei;
    const int* col = ei + N_EDGES;

    k_prep<<<EW_BLKS + NBLK_NODES, 256>>>(emb, W1);
    k_deg<<<(N_EDGES / 4 + 255) / 256, 256>>>(col, pos);
    k_coef<<<(N_EDGES / 4 + 255) / 256, 256>>>(row, col);
    k_alloc<<<NBLK_NODES, 256>>>();
    k_csr<<<(N_EDGES / 4 + 255) / 256, 256>>>(row, col, x);
    k_gather<<<1184, 256>>>(b1, x);
    k_out<<<VOCABSZ / 256, 256>>>(W2, b2, Wc, bc, out);
}

// round 6
// speedup vs baseline: 1.2362x; 1.0849x over previous
#include <cuda_runtime.h>
#include <cuda_bf16.h>

#define N_NODES 50000
#define N_EDGES 800000
#define VOCABSZ 4096
#define EMB_DIM 128
#define H2 256      // 2*HIDDEN
#define HID 128
#define N_POS 1024
#define NBLK_NODES 196   // ceil(50000/256)
#define EW_BLKS 256      // 4096/16

// ---------------- scratch (device globals) ----------------------------------
__device__ uint4 d_EWh[VOCABSZ * 32];       // emb @ W1 in bf16x2, 2 MB (L2-resident)
__device__ int   d_dc[2 * N_NODES];         // interleaved {deg, cnt} per node
__device__ float d_coef[N_NODES];           // layer-2 edge weight per source node
__device__ unsigned char d_need[N_NODES];   // h1 needed at this node?
__device__ int   d_start[N_NODES];          // CSR start (unordered segments)
__device__ int   d_cursor[N_NODES];         // CSR fill cursor
__device__ int   d_list[N_NODES];           // compact list of needed nodes
__device__ int   d_nneed;
__device__ int   d_total;
__device__ int2  d_csr[N_EDGES];            // {x[row], bits(dinv_r*dinv_c)}
__device__ float d_svec[H2];

__device__ __forceinline__ void red4(float4* p, float a, float b, float c, float d) {
    asm volatile("red.global.add.v4.f32 [%0], {%1,%2,%3,%4};"
                 :: "l"(p), "f"(a), "f"(b), "f"(c), "f"(d) : "memory");
}

// accumulate 8 bf16 values (packed in a uint4) scaled by w into a[8]
__device__ __forceinline__ void acc8(float* a, uint4 q, float w) {
    float2 f0 = __bfloat1622float2(*(const __nv_bfloat162*)&q.x);
    float2 f1 = __bfloat1622float2(*(const __nv_bfloat162*)&q.y);
    float2 f2 = __bfloat1622float2(*(const __nv_bfloat162*)&q.z);
    float2 f3 = __bfloat1622float2(*(const __nv_bfloat162*)&q.w);
    a[0] += w * f0.x; a[1] += w * f0.y;
    a[2] += w * f1.x; a[3] += w * f1.y;
    a[4] += w * f2.x; a[5] += w * f2.y;
    a[6] += w * f3.x; a[7] += w * f3.y;
}

// ---------------- K0: fused EW-GEMM (blocks 0..255) + zero (blocks 256..) ---
__global__ void __launch_bounds__(256) k_prep(const float* __restrict__ emb,
                                              const float* __restrict__ W1) {
    if (blockIdx.x < EW_BLKS) {
        __shared__ float se[16 * 128];
        int t0 = blockIdx.x * 16;
        for (int i = threadIdx.x; i < 16 * 128; i += 256) se[i] = emb[t0 * 128 + i];
        __syncthreads();
        int j = threadIdx.x;   // output column 0..255
        float acc[16];
#pragma unroll
        for (int r = 0; r < 16; r++) acc[r] = 0.f;
        for (int k = 0; k < 128; k++) {
            float w = W1[k * H2 + j];
#pragma unroll
            for (int r = 0; r < 16; r++) acc[r] += se[r * 128 + k] * w;
        }
        unsigned* EWu = (unsigned*)d_EWh;
#pragma unroll
        for (int r = 0; r < 16; r++) {
            float v = acc[r];
            float vh = __shfl_down_sync(0xffffffffu, v, 1);
            if ((j & 1) == 0) {
                __nv_bfloat162 h = __floats2bfloat162_rn(v, vh);
                EWu[(t0 + r) * 128 + (j >> 1)] = *(unsigned*)&h;
            }
        }
    } else {
        int i = (blockIdx.x - EW_BLKS) * 256 + threadIdx.x;
        if (i < N_NODES) {
            d_dc[2 * i] = 0; d_dc[2 * i + 1] = 0;
            d_coef[i] = 0.f; d_need[i] = 0;
        }
        if (i < H2) d_svec[i] = 0.f;
        if (i == 0) { d_nneed = 0; d_total = 0; }
    }
}

// ---------------- K1: degree + selected-count + need[pos] -------------------
__global__ void __launch_bounds__(256) k_deg(const int* __restrict__ col,
                                             const int* __restrict__ pos) {
    int i4 = blockIdx.x * blockDim.x + threadIdx.x;
    if (i4 < N_EDGES / 4) {
        int4 c = ((const int4*)col)[i4];
        atomicAdd(&d_dc[2 * c.x], 1);
        atomicAdd(&d_dc[2 * c.y], 1);
        atomicAdd(&d_dc[2 * c.z], 1);
        atomicAdd(&d_dc[2 * c.w], 1);
    }
    if (i4 < N_POS) {
        int p = pos[i4];
        atomicAdd(&d_dc[2 * p + 1], 1);
        d_need[p] = 1;
    }
}

// ---------------- K2: per-source coef + need flags (int4, on-the-fly dinv) --
__global__ void __launch_bounds__(256) k_coef(const int* __restrict__ row,
                                              const int* __restrict__ col) {
    int i4 = blockIdx.x * blockDim.x + threadIdx.x;
    if (i4 >= N_EDGES / 4) return;
    int4 c = ((const int4*)col)[i4];
    int4 r = ((const int4*)row)[i4];
#define DO_E(rr, cc) { \
    int2 dcc = *(const int2*)&d_dc[2 * (cc)]; \
    if (dcc.y > 0) { \
        float w = rsqrtf((float)d_dc[2 * (rr)] + 1.f) * rsqrtf((float)dcc.x + 1.f) * (float)dcc.y; \
        atomicAdd(&d_coef[rr], w); \
        d_need[rr] = 1; \
    } }
    DO_E(r.x, c.x) DO_E(r.y, c.y) DO_E(r.z, c.z) DO_E(r.w, c.w)
#undef DO_E
}

// ---------------- K3: warp-aggregated CSR range allocation ------------------
__global__ void __launch_bounds__(256) k_alloc() {
    int u = blockIdx.x * 256 + threadIdx.x;
    int lane = threadIdx.x & 31;
    bool act = (u < N_NODES) && (d_need[u] != 0);
    int deg = act ? d_dc[2 * u] : 0;
    // warp-inclusive prefix sum of deg
    int pre = deg;
#pragma unroll
    for (int o = 1; o < 32; o <<= 1) {
        int v = __shfl_up_sync(0xffffffffu, pre, o);
        if (lane >= o) pre += v;
    }
    int wtot = __shfl_sync(0xffffffffu, pre, 31);
    int excl = pre - deg;
    unsigned m = __ballot_sync(0xffffffffu, act);
    int wcnt = __popc(m);
    int rank = __popc(m & ((1u << lane) - 1));
    int baseS = 0, baseL = 0;
    if (lane == 0 && wtot > 0) baseS = atomicAdd(&d_total, wtot);
    if (lane == 0 && wcnt > 0) baseL = atomicAdd(&d_nneed, wcnt);
    baseS = __shfl_sync(0xffffffffu, baseS, 0);
    baseL = __shfl_sync(0xffffffffu, baseL, 0);
    if (act) {
        int st = baseS + excl;
        d_start[u] = st;
        d_cursor[u] = st;
        d_list[baseL + rank] = u;
    }
}

// ---------------- K4: CSR build (int4) --------------------------------------
__global__ void __launch_bounds__(256) k_csr(const int* __restrict__ row,
                                             const int* __restrict__ col,
                                             const int* __restrict__ x) {
    int i4 = blockIdx.x * blockDim.x + threadIdx.x;
    if (i4 >= N_EDGES / 4) return;
    int4 c = ((const int4*)col)[i4];
    int4 r = ((const int4*)row)[i4];
#define DO_E(rr, cc) \
    if (d_need[cc]) { \
        int idx = atomicAdd(&d_cursor[cc], 1); \
        float w = rsqrtf((float)d_dc[2 * (rr)] + 1.f) * rsqrtf((float)d_dc[2 * (cc)] + 1.f); \
        d_csr[idx] = make_int2(x[rr], __float_as_int(w)); \
    }
    DO_E(r.x, c.x) DO_E(r.y, c.y) DO_E(r.z, c.z) DO_E(r.w, c.w)
#undef DO_E
}

// ---------------- K5: fused gather (bf16 EW): h1 + relu + layer-2 reduction -
// warp-per-node; each lane owns output cols [8*lane, 8*lane+8)
__global__ void __launch_bounds__(256) k_gather(const float* __restrict__ b1,
                                                const int* __restrict__ x) {
    __shared__ float ssv[H2];
    int tid = threadIdx.x;
    ssv[tid] = 0.f;
    __syncthreads();
    int lane = tid & 31;
    int gw = (blockIdx.x * blockDim.x + tid) >> 5;
    int nw = (gridDim.x * blockDim.x) >> 5;
    int nn = d_nneed;
    float4 bq0 = ((const float4*)b1)[2 * lane];
    float4 bq1 = ((const float4*)b1)[2 * lane + 1];
    float sv[8];
#pragma unroll
    for (int k = 0; k < 8; k++) sv[k] = 0.f;
    for (int idx = gw; idx < nn; idx += nw) {
        int u = d_list[idx];
        int2 dcu = *(const int2*)&d_dc[2 * u];
        float du = rsqrtf((float)dcu.x + 1.f);
        float d2 = du * du;
        int toku = x[u];
        float a[8];
#pragma unroll
        for (int k = 0; k < 8; k++) a[k] = 0.f;
        acc8(a, d_EWh[(size_t)toku * 32 + lane], d2);
        int s0 = d_start[u], len = dcu.x;
        for (int b = 0; b < len; b += 32) {
            int i = b + lane;
            int2 ev = (i < len) ? d_csr[s0 + i] : make_int2(0, 0);
            float wl = (i < len) ? __int_as_float(ev.y) : 0.f;
            int n4 = (min(32, len - b) + 3) & ~3;
            for (int j = 0; j < n4; j += 4) {
                int t0 = __shfl_sync(0xffffffffu, ev.x, j + 0);
                int t1 = __shfl_sync(0xffffffffu, ev.x, j + 1);
                int t2 = __shfl_sync(0xffffffffu, ev.x, j + 2);
                int t3 = __shfl_sync(0xffffffffu, ev.x, j + 3);
                float w0 = __shfl_sync(0xffffffffu, wl, j + 0);
                float w1 = __shfl_sync(0xffffffffu, wl, j + 1);
                float w2 = __shfl_sync(0xffffffffu, wl, j + 2);
                float w3 = __shfl_sync(0xffffffffu, wl, j + 3);
                uint4 q0 = d_EWh[(size_t)t0 * 32 + lane];
                uint4 q1 = d_EWh[(size_t)t1 * 32 + lane];
                uint4 q2 = d_EWh[(size_t)t2 * 32 + lane];
                uint4 q3 = d_EWh[(size_t)t3 * 32 + lane];
                acc8(a, q0, w0);
                acc8(a, q1, w1);
                acc8(a, q2, w2);
                acc8(a, q3, w3);
            }
        }
        float ct = d_coef[u] + (float)dcu.y * d2;
        sv[0] += ct * fmaxf(a[0] + bq0.x, 0.f);
        sv[1] += ct * fmaxf(a[1] + bq0.y, 0.f);
        sv[2] += ct * fmaxf(a[2] + bq0.z, 0.f);
        sv[3] += ct * fmaxf(a[3] + bq0.w, 0.f);
        sv[4] += ct * fmaxf(a[4] + bq1.x, 0.f);
        sv[5] += ct * fmaxf(a[5] + bq1.y, 0.f);
        sv[6] += ct * fmaxf(a[6] + bq1.z, 0.f);
        sv[7] += ct * fmaxf(a[7] + bq1.w, 0.f);
    }
#pragma unroll
    for (int k = 0; k < 8; k++) atomicAdd(&ssv[8 * lane + k], sv[k]);
    __syncthreads();
    if (tid < 64) {
        float4 p = ((float4*)ssv)[tid];
        red4(((float4*)d_svec) + tid, p.x, p.y, p.z, p.w);
    }
}

// ---------------- K6: fused zbar + classifier -------------------------------
__global__ void __launch_bounds__(256) k_out(const float* __restrict__ W2,
                                             const float* __restrict__ b2,
                                             const float* __restrict__ Wc,
                                             const float* __restrict__ bc,
                                             float* __restrict__ out) {
    __shared__ float zb[HID];
    int t = threadIdx.x;
    if (t < HID) {
        float acc = 0.f;
        for (int k = 0; k < H2; k++) acc += d_svec[k] * W2[k * HID + t];
        zb[t] = acc * (1.0f / (float)N_POS) + b2[t];
    }
    __syncthreads();
    int c = blockIdx.x * 256 + t;
    float acc = bc[c];
#pragma unroll 8
    for (int j = 0; j < HID; j++) acc += zb[j] * Wc[j * VOCABSZ + c];
    out[c] = acc;
}

extern "C" void kernel_launch(void* const* d_in, const int* in_sizes, int n_in,
                              void* d_out, int out_size) {
    const int*   x    = (const int*)d_in[0];
    const int*   ei   = (const int*)d_in[1];
    const int*   pos  = (const int*)d_in[2];
    const float* emb  = (const float*)d_in[3];
    const float* W1   = (const float*)d_in[4];
    const float* b1   = (const float*)d_in[5];
    const float* W2   = (const float*)d_in[6];
    const float* b2   = (const float*)d_in[7];
    const float* Wc   = (const float*)d_in[8];
    const float* bc   = (const float*)d_in[9];
    float* out = (float*)d_out;
    const int* row = ei;
    const int* col = ei + N_EDGES;

    k_prep<<<EW_BLKS + NBLK_NODES, 256>>>(emb, W1);
    k_deg<<<(N_EDGES / 4 + 255) / 256, 256>>>(col, pos);
    k_coef<<<(N_EDGES / 4 + 255) / 256, 256>>>(row, col);
    k_alloc<<<NBLK_NODES, 256>>>();
    k_csr<<<(N_EDGES / 4 + 255) / 256, 256>>>(row, col, x);
    k_gather<<<1184, 256>>>(b1, x);
    k_out<<<VOCABSZ / 256, 256>>>(W2, b2, Wc, bc, out);
}

// round 7
// speedup vs baseline: 1.3426x; 1.0861x over previous
#include <cuda_runtime.h>
#include <cuda_bf16.h>

#define N_NODES 50000
#define N_EDGES 800000
#define VOCABSZ 4096
#define EMB_DIM 128
#define H2 256      // 2*HIDDEN
#define HID 128
#define N_POS 1024

#define GRID_BUILD 740
#define EWB 256                      // EW-GEMM blocks (4096/16 tiles)
#define NWORK (GRID_BUILD - EWB)     // 484 worker blocks (barrier participants)
#define NT (NWORK * 256)             // 123904 worker threads (covers N_NODES in 1 pass)

// ---------------- scratch (device globals) ----------------------------------
__device__ uint4 d_EWh[VOCABSZ * 32];       // emb @ W1 in bf16x2, 2 MB (L2-resident)
__device__ int   d_dc[2 * N_NODES];         // interleaved {deg, cnt} per node
__device__ float d_coef[N_NODES];           // layer-2 edge weight per source node
__device__ unsigned char d_need[N_NODES];   // h1 needed at this node?
__device__ int   d_start[N_NODES];          // CSR start (unordered segments)
__device__ int   d_cursor[N_NODES];         // CSR fill cursor
__device__ int   d_list[N_NODES];           // compact list of needed nodes
__device__ int   d_nneed;
__device__ int   d_total;
__device__ int   d_csr1[N_EDGES];           // packed: (x[row]<<16) | bf16bits(dinv_r*dinv_c)
__device__ float d_svec[H2];
__device__ int   d_bar[8];                  // software barrier counters (reset by k_gather)

__device__ __forceinline__ void red4(float4* p, float a, float b, float c, float d) {
    asm volatile("red.global.add.v4.f32 [%0], {%1,%2,%3,%4};"
                 :: "l"(p), "f"(a), "f"(b), "f"(c), "f"(d) : "memory");
}

// accumulate 8 bf16 values (packed in a uint4) scaled by w into a[8]
__device__ __forceinline__ void acc8(float* a, uint4 q, float w) {
    float2 f0 = __bfloat1622float2(*(const __nv_bfloat162*)&q.x);
    float2 f1 = __bfloat1622float2(*(const __nv_bfloat162*)&q.y);
    float2 f2 = __bfloat1622float2(*(const __nv_bfloat162*)&q.z);
    float2 f3 = __bfloat1622float2(*(const __nv_bfloat162*)&q.w);
    a[0] += w * f0.x; a[1] += w * f0.y;
    a[2] += w * f1.x; a[3] += w * f1.y;
    a[4] += w * f2.x; a[5] += w * f2.y;
    a[6] += w * f3.x; a[7] += w * f3.y;
}

// worker-only global barrier (NWORK blocks; EW blocks never call this)
__device__ __forceinline__ void wbar(int i) {
    __syncthreads();
    if (threadIdx.x == 0) {
        __threadfence();
        atomicAdd(&d_bar[i], 1);
        while (*(volatile int*)&d_bar[i] < NWORK) __nanosleep(64);
    }
    __syncthreads();
}

__device__ __forceinline__ unsigned short f2bf(float w) {
    unsigned u = __float_as_uint(w);
    u += 0x7fffu + ((u >> 16) & 1u);   // round-to-nearest-even
    return (unsigned short)(u >> 16);
}

// ---------------- K0: everything before the gather, in one kernel -----------
__global__ void __launch_bounds__(256, 5) k_build(
    const float* __restrict__ emb, const float* __restrict__ W1,
    const int* __restrict__ row, const int* __restrict__ col,
    const int* __restrict__ pos, const int* __restrict__ x)
{
    if (blockIdx.x < EWB) {
        // ---- EW GEMM blocks: EW = bf16(emb @ W1); no barriers, exit early ---
        __shared__ float se[16 * 128];
        int t0 = blockIdx.x * 16;
        for (int i = threadIdx.x; i < 16 * 128; i += 256) se[i] = emb[t0 * 128 + i];
        __syncthreads();
        int j = threadIdx.x;
        float acc[16];
#pragma unroll
        for (int r = 0; r < 16; r++) acc[r] = 0.f;
        for (int k = 0; k < 128; k++) {
            float w = W1[k * H2 + j];
#pragma unroll
            for (int r = 0; r < 16; r++) acc[r] += se[r * 128 + k] * w;
        }
        unsigned* EWu = (unsigned*)d_EWh;
#pragma unroll
        for (int r = 0; r < 16; r++) {
            float v = acc[r];
            float vh = __shfl_down_sync(0xffffffffu, v, 1);
            if ((j & 1) == 0) {
                __nv_bfloat162 h = __floats2bfloat162_rn(v, vh);
                EWu[(t0 + r) * 128 + (j >> 1)] = *(unsigned*)&h;
            }
        }
        return;
    }

    // ---- worker blocks ------------------------------------------------------
    int wb = blockIdx.x - EWB;
    int gtid = wb * 256 + threadIdx.x;

    // stage Z: zero counters (NT >= N_NODES: single pass)
    if (gtid < N_NODES) {
        d_dc[2 * gtid] = 0; d_dc[2 * gtid + 1] = 0;
        d_coef[gtid] = 0.f; d_need[gtid] = 0;
    }
    if (gtid < H2) d_svec[gtid] = 0.f;
    if (gtid == 0) { d_total = 0; d_nneed = 0; }
    wbar(0);

    // stage A: degree (edges) + cnt/need (positions)
    for (int i4 = gtid; i4 < N_EDGES / 4; i4 += NT) {
        int4 c = __ldcg(&((const int4*)col)[i4]);
        atomicAdd(&d_dc[2 * c.x], 1);
        atomicAdd(&d_dc[2 * c.y], 1);
        atomicAdd(&d_dc[2 * c.z], 1);
        atomicAdd(&d_dc[2 * c.w], 1);
    }
    if (gtid < N_POS) {
        int p = __ldcg(&pos[gtid]);
        atomicAdd(&d_dc[2 * p + 1], 1);
        d_need[p] = 1;
    }
    wbar(1);

    // stage B: per-source coef + need flags
    for (int i4 = gtid; i4 < N_EDGES / 4; i4 += NT) {
        int4 c = __ldcg(&((const int4*)col)[i4]);
        int4 r = __ldcg(&((const int4*)row)[i4]);
#define DO_E(rr, cc) { \
        int dg = __ldcg(&d_dc[2 * (cc)]); \
        int ct = __ldcg(&d_dc[2 * (cc) + 1]); \
        if (ct > 0) { \
            float w = rsqrtf((float)__ldcg(&d_dc[2 * (rr)]) + 1.f) * rsqrtf((float)dg + 1.f) * (float)ct; \
            atomicAdd(&d_coef[rr], w); \
            d_need[rr] = 1; \
        } }
        DO_E(r.x, c.x) DO_E(r.y, c.y) DO_E(r.z, c.z) DO_E(r.w, c.w)
#undef DO_E
    }
    wbar(2);

    // stage C: warp-aggregated CSR range allocation (NT >= N_NODES: single pass)
    {
        int u = gtid;
        int lane = threadIdx.x & 31;
        bool act = (u < N_NODES) && (__ldcg(&d_need[u]) != 0);
        int deg = act ? __ldcg(&d_dc[2 * u]) : 0;
        int pre = deg;
#pragma unroll
        for (int o = 1; o < 32; o <<= 1) {
            int v = __shfl_up_sync(0xffffffffu, pre, o);
            if (lane >= o) pre += v;
        }
        int wtot = __shfl_sync(0xffffffffu, pre, 31);
        int excl = pre - deg;
        unsigned m = __ballot_sync(0xffffffffu, act);
        int wcnt = __popc(m);
        int rank = __popc(m & ((1u << lane) - 1));
        int baseS = 0, baseL = 0;
        if (lane == 0 && wtot > 0) baseS = atomicAdd(&d_total, wtot);
        if (lane == 0 && wcnt > 0) baseL = atomicAdd(&d_nneed, wcnt);
        baseS = __shfl_sync(0xffffffffu, baseS, 0);
        baseL = __shfl_sync(0xffffffffu, baseL, 0);
        if (act) {
            int st = baseS + excl;
            d_start[u] = st;
            d_cursor[u] = st;
            d_list[baseL + rank] = u;
        }
    }
    wbar(3);

    // stage D: packed CSR build
    for (int i4 = gtid; i4 < N_EDGES / 4; i4 += NT) {
        int4 c = __ldcg(&((const int4*)col)[i4]);
        int4 r = __ldcg(&((const int4*)row)[i4]);
#define DO_E(rr, cc) \
        if (__ldcg(&d_need[cc])) { \
            int idx = atomicAdd(&d_cursor[cc], 1); \
            float w = rsqrtf((float)__ldcg(&d_dc[2 * (rr)]) + 1.f) * rsqrtf((float)__ldcg(&d_dc[2 * (cc)]) + 1.f); \
            d_csr1[idx] = (__ldcg(&x[rr]) << 16) | (int)f2bf(w); \
        }
        DO_E(r.x, c.x) DO_E(r.y, c.y) DO_E(r.z, c.z) DO_E(r.w, c.w)
#undef DO_E
    }
}

// ---------------- K1: fused gather (bf16 EW): h1 + relu + layer-2 reduction -
__global__ void __launch_bounds__(256) k_gather(const float* __restrict__ b1,
                                                const int* __restrict__ x) {
    __shared__ float ssv[H2];
    int tid = threadIdx.x;
    ssv[tid] = 0.f;
    if (blockIdx.x == 0 && tid < 8) d_bar[tid] = 0;   // reset barrier for next replay
    __syncthreads();
    int lane = tid & 31;
    int gw = (blockIdx.x * blockDim.x + tid) >> 5;
    int nw = (gridDim.x * blockDim.x) >> 5;
    int nn = d_nneed;
    float4 bq0 = ((const float4*)b1)[2 * lane];
    float4 bq1 = ((const float4*)b1)[2 * lane + 1];
    float sv[8];
#pragma unroll
    for (int k = 0; k < 8; k++) sv[k] = 0.f;
    for (int idx = gw; idx < nn; idx += nw) {
        int u = d_list[idx];
        int2 dcu = *(const int2*)&d_dc[2 * u];
        float du = rsqrtf((float)dcu.x + 1.f);
        float d2 = du * du;
        int toku = x[u];
        float a[8];
#pragma unroll
        for (int k = 0; k < 8; k++) a[k] = 0.f;
        acc8(a, d_EWh[(size_t)toku * 32 + lane], d2);
        int s0 = d_start[u], len = dcu.x;
        for (int b = 0; b < len; b += 32) {
            int i = b + lane;
            int ev = (i < len) ? d_csr1[s0 + i] : 0;   // 0 => w = +0.0f
            int n4 = (min(32, len - b) + 3) & ~3;
            for (int j = 0; j < n4; j += 4) {
                int e0 = __shfl_sync(0xffffffffu, ev, j + 0);
                int e1 = __shfl_sync(0xffffffffu, ev, j + 1);
                int e2 = __shfl_sync(0xffffffffu, ev, j + 2);
                int e3 = __shfl_sync(0xffffffffu, ev, j + 3);
                uint4 q0 = d_EWh[(size_t)(e0 >> 16) * 32 + lane];
                uint4 q1 = d_EWh[(size_t)(e1 >> 16) * 32 + lane];
                uint4 q2 = d_EWh[(size_t)(e2 >> 16) * 32 + lane];
                uint4 q3 = d_EWh[(size_t)(e3 >> 16) * 32 + lane];
                acc8(a, q0, __uint_as_float((unsigned)e0 << 16));
                acc8(a, q1, __uint_as_float((unsigned)e1 << 16));
                acc8(a, q2, __uint_as_float((unsigned)e2 << 16));
                acc8(a, q3, __uint_as_float((unsigned)e3 << 16));
            }
        }
        float ct = d_coef[u] + (float)dcu.y * d2;
        sv[0] += ct * fmaxf(a[0] + bq0.x, 0.f);
        sv[1] += ct * fmaxf(a[1] + bq0.y, 0.f);
        sv[2] += ct * fmaxf(a[2] + bq0.z, 0.f);
        sv[3] += ct * fmaxf(a[3] + bq0.w, 0.f);
        sv[4] += ct * fmaxf(a[4] + bq1.x, 0.f);
        sv[5] += ct * fmaxf(a[5] + bq1.y, 0.f);
        sv[6] += ct * fmaxf(a[6] + bq1.z, 0.f);
        sv[7] += ct * fmaxf(a[7] + bq1.w, 0.f);
    }
#pragma unroll
    for (int k = 0; k < 8; k++) atomicAdd(&ssv[8 * lane + k], sv[k]);
    __syncthreads();
    if (tid < 64) {
        float4 p = ((float4*)ssv)[tid];
        red4(((float4*)d_svec) + tid, p.x, p.y, p.z, p.w);
    }
}

// ---------------- K2: fused zbar + classifier -------------------------------
__global__ void __launch_bounds__(256) k_out(const float* __restrict__ W2,
                                             const float* __restrict__ b2,
                                             const float* __restrict__ Wc,
                                             const float* __restrict__ bc,
                                             float* __restrict__ out) {
    __shared__ float zb[HID];
    int t = threadIdx.x;
    if (t < HID) {
        float acc = 0.f;
        for (int k = 0; k < H2; k++) acc += d_svec[k] * W2[k * HID + t];
        zb[t] = acc * (1.0f / (float)N_POS) + b2[t];
    }
    __syncthreads();
    int c = blockIdx.x * 256 + t;
    float acc = bc[c];
#pragma unroll 8
    for (int j = 0; j < HID; j++) acc += zb[j] * Wc[j * VOCABSZ + c];
    out[c] = acc;
}

extern "C" void kernel_launch(void* const* d_in, const int* in_sizes, int n_in,
                              void* d_out, int out_size) {
    const int*   x    = (const int*)d_in[0];
    const int*   ei   = (const int*)d_in[1];
    const int*   pos  = (const int*)d_in[2];
    const float* emb  = (const float*)d_in[3];
    const float* W1   = (const float*)d_in[4];
    const float* b1   = (const float*)d_in[5];
    const float* W2   = (const float*)d_in[6];
    const float* b2   = (const float*)d_in[7];
    const float* Wc   = (const float*)d_in[8];
    const float* bc   = (const float*)d_in[9];
    float* out = (float*)d_out;
    const int* row = ei;
    const int* col = ei + N_EDGES;

    k_build<<<GRID_BUILD, 256>>>(emb, W1, row, col, pos, x);
    k_gather<<<1184, 256>>>(b1, x);
    k_out<<<VOCABSZ / 256, 256>>>(W2, b2, Wc, bc, out);
}

// round 8
// speedup vs baseline: 1.3694x; 1.0200x over previous
#include <cuda_runtime.h>
#include <cuda_bf16.h>

#define N_NODES 50000
#define N_EDGES 800000
#define VOCABSZ 4096
#define EMB_DIM 128
#define H2 256      // 2*HIDDEN
#define HID 128
#define N_POS 1024

#define GRID_BUILD 740
#define EWB 256                      // EW-GEMM blocks (4096/16 tiles)
#define NWORK (GRID_BUILD - EWB)     // 484 worker blocks (barrier participants)
#define NT (NWORK * 256)             // 123904 worker threads

#define OUT_BLKS 16                  // classifier blocks
#define ZERO_BLKS 84                 // state-zeroing blocks appended to k_out

// ---------------- scratch (device globals; zero-initialized at module load) -
__device__ uint4 d_EWh[VOCABSZ * 32];       // emb @ W1 in bf16x2, 2 MB
__device__ int   d_dc[2 * N_NODES];         // interleaved {deg, cnt} per node
__device__ float d_coef[N_NODES];           // layer-2 edge weight per source node
__device__ unsigned char d_need[N_NODES];   // h1 needed at this node?
__device__ int   d_start[N_NODES];          // CSR start (unordered segments)
__device__ int   d_cursor[N_NODES];         // CSR fill cursor
__device__ int   d_list[N_NODES];           // compact list of needed nodes
__device__ int   d_nneed;
__device__ int   d_total;
__device__ int   d_csr1[N_EDGES];           // packed: (x[row]<<16) | bf16bits(w)
__device__ float d_svec[H2];
__device__ int   d_bar[8];                  // software barrier counters

__device__ __forceinline__ void red4(float4* p, float a, float b, float c, float d) {
    asm volatile("red.global.add.v4.f32 [%0], {%1,%2,%3,%4};"
                 :: "l"(p), "f"(a), "f"(b), "f"(c), "f"(d) : "memory");
}

__device__ __forceinline__ void acc8(float* a, uint4 q, float w) {
    float2 f0 = __bfloat1622float2(*(const __nv_bfloat162*)&q.x);
    float2 f1 = __bfloat1622float2(*(const __nv_bfloat162*)&q.y);
    float2 f2 = __bfloat1622float2(*(const __nv_bfloat162*)&q.z);
    float2 f3 = __bfloat1622float2(*(const __nv_bfloat162*)&q.w);
    a[0] += w * f0.x; a[1] += w * f0.y;
    a[2] += w * f1.x; a[3] += w * f1.y;
    a[4] += w * f2.x; a[5] += w * f2.y;
    a[6] += w * f3.x; a[7] += w * f3.y;
}

// worker-only global barrier (NWORK blocks; EW blocks never call this)
__device__ __forceinline__ void wbar(int i) {
    __syncthreads();
    if (threadIdx.x == 0) {
        __threadfence();
        atomicAdd(&d_bar[i], 1);
        while (*(volatile int*)&d_bar[i] < NWORK) __nanosleep(64);
    }
    __syncthreads();
}

__device__ __forceinline__ unsigned short f2bf(float w) {
    unsigned u = __float_as_uint(w);
    u += 0x7fffu + ((u >> 16) & 1u);   // round-to-nearest-even
    return (unsigned short)(u >> 16);
}

// ---------------- K0: EW GEMM (blocks 0..255) + build pipeline (256..739) ---
__global__ void __launch_bounds__(256, 5) k_build(
    const float* __restrict__ emb, const float* __restrict__ W1,
    const int* __restrict__ row, const int* __restrict__ col,
    const int* __restrict__ pos, const int* __restrict__ x)
{
    if (blockIdx.x < EWB) {
        // ---- EW GEMM blocks: EW = bf16(emb @ W1); no barriers, exit early ---
        __shared__ float se[16 * 128];
        int t0 = blockIdx.x * 16;
        for (int i = threadIdx.x; i < 16 * 128; i += 256) se[i] = emb[t0 * 128 + i];
        __syncthreads();
        int j = threadIdx.x;
        float acc[16];
#pragma unroll
        for (int r = 0; r < 16; r++) acc[r] = 0.f;
        for (int k = 0; k < 128; k++) {
            float w = W1[k * H2 + j];
#pragma unroll
            for (int r = 0; r < 16; r++) acc[r] += se[r * 128 + k] * w;
        }
        unsigned* EWu = (unsigned*)d_EWh;
#pragma unroll
        for (int r = 0; r < 16; r++) {
            float v = acc[r];
            float vh = __shfl_down_sync(0xffffffffu, v, 1);
            if ((j & 1) == 0) {
                __nv_bfloat162 h = __floats2bfloat162_rn(v, vh);
                EWu[(t0 + r) * 128 + (j >> 1)] = *(unsigned*)&h;
            }
        }
        return;
    }

    // ---- worker blocks (state arrives pre-zeroed from previous k_out) ------
    int wb = blockIdx.x - EWB;
    int gtid = wb * 256 + threadIdx.x;

    // stage P: cnt/need from positions; zero svec for the coming gather
    if (gtid < N_POS) {
        int p = __ldcg(&pos[gtid]);
        atomicAdd(&d_dc[2 * p + 1], 1);
        d_need[p] = 1;
    }
    if (gtid < H2) d_svec[gtid] = 0.f;
    wbar(0);

    // stage AB: ONE edge scan: degree atomics + need flags (cnt is final)
    for (int i4 = gtid; i4 < N_EDGES / 4; i4 += NT) {
        int4 c = __ldcg(&((const int4*)col)[i4]);
        int4 r = __ldcg(&((const int4*)row)[i4]);
        atomicAdd(&d_dc[2 * c.x], 1);
        atomicAdd(&d_dc[2 * c.y], 1);
        atomicAdd(&d_dc[2 * c.z], 1);
        atomicAdd(&d_dc[2 * c.w], 1);
        if (__ldcg(&d_dc[2 * c.x + 1]) > 0) d_need[r.x] = 1;
        if (__ldcg(&d_dc[2 * c.y + 1]) > 0) d_need[r.y] = 1;
        if (__ldcg(&d_dc[2 * c.z + 1]) > 0) d_need[r.z] = 1;
        if (__ldcg(&d_dc[2 * c.w + 1]) > 0) d_need[r.w] = 1;
    }
    wbar(1);

    // stage C: warp-aggregated CSR range allocation (NT >= N_NODES)
    {
        int u = gtid;
        int lane = threadIdx.x & 31;
        bool act = (u < N_NODES) && (__ldcg(&d_need[u]) != 0);
        int deg = act ? __ldcg(&d_dc[2 * u]) : 0;
        int pre = deg;
#pragma unroll
        for (int o = 1; o < 32; o <<= 1) {
            int v = __shfl_up_sync(0xffffffffu, pre, o);
            if (lane >= o) pre += v;
        }
        int wtot = __shfl_sync(0xffffffffu, pre, 31);
        int excl = pre - deg;
        unsigned m = __ballot_sync(0xffffffffu, act);
        int wcnt = __popc(m);
        int rank = __popc(m & ((1u << lane) - 1));
        int baseS = 0, baseL = 0;
        if (lane == 0 && wtot > 0) baseS = atomicAdd(&d_total, wtot);
        if (lane == 0 && wcnt > 0) baseL = atomicAdd(&d_nneed, wcnt);
        baseS = __shfl_sync(0xffffffffu, baseS, 0);
        baseL = __shfl_sync(0xffffffffu, baseL, 0);
        if (act) {
            int st = baseS + excl;
            d_start[u] = st;
            d_cursor[u] = st;
            d_list[baseL + rank] = u;
        }
    }
    wbar(2);

    // stage D: packed CSR build + coef accumulation (one edge scan)
    for (int i4 = gtid; i4 < N_EDGES / 4; i4 += NT) {
        int4 c = __ldcg(&((const int4*)col)[i4]);
        int4 r = __ldcg(&((const int4*)row)[i4]);
#define DO_E(rr, cc) \
        if (__ldcg(&d_need[cc])) { \
            int idx = atomicAdd(&d_cursor[cc], 1); \
            float w = rsqrtf((float)__ldcg(&d_dc[2 * (rr)]) + 1.f) * rsqrtf((float)__ldcg(&d_dc[2 * (cc)]) + 1.f); \
            d_csr1[idx] = (__ldcg(&x[rr]) << 16) | (int)f2bf(w); \
            int ct = __ldcg(&d_dc[2 * (cc) + 1]); \
            if (ct > 0) atomicAdd(&d_coef[rr], w * (float)ct); \
        }
        DO_E(r.x, c.x) DO_E(r.y, c.y) DO_E(r.z, c.z) DO_E(r.w, c.w)
#undef DO_E
    }
}

// ---------------- K1: fused gather (bf16 EW): h1 + relu + layer-2 reduction -
__global__ void __launch_bounds__(256) k_gather(const float* __restrict__ b1,
                                                const int* __restrict__ x) {
    __shared__ float ssv[H2];
    int tid = threadIdx.x;
    ssv[tid] = 0.f;
    __syncthreads();
    int lane = tid & 31;
    int gw = (blockIdx.x * blockDim.x + tid) >> 5;
    int nw = (gridDim.x * blockDim.x) >> 5;
    int nn = d_nneed;
    float4 bq0 = ((const float4*)b1)[2 * lane];
    float4 bq1 = ((const float4*)b1)[2 * lane + 1];
    float sv[8];
#pragma unroll
    for (int k = 0; k < 8; k++) sv[k] = 0.f;
    for (int idx = gw; idx < nn; idx += nw) {
        int u = d_list[idx];
        int2 dcu = *(const int2*)&d_dc[2 * u];
        float du = rsqrtf((float)dcu.x + 1.f);
        float d2 = du * du;
        int toku = x[u];
        float a[8];
#pragma unroll
        for (int k = 0; k < 8; k++) a[k] = 0.f;
        acc8(a, d_EWh[(size_t)toku * 32 + lane], d2);
        int s0 = d_start[u], len = dcu.x;
        for (int b = 0; b < len; b += 32) {
            int i = b + lane;
            int ev = (i < len) ? d_csr1[s0 + i] : 0;   // 0 => w = +0.0f
            int n4 = (min(32, len - b) + 3) & ~3;
            for (int j = 0; j < n4; j += 4) {
                int e0 = __shfl_sync(0xffffffffu, ev, j + 0);
                int e1 = __shfl_sync(0xffffffffu, ev, j + 1);
                int e2 = __shfl_sync(0xffffffffu, ev, j + 2);
                int e3 = __shfl_sync(0xffffffffu, ev, j + 3);
                uint4 q0 = d_EWh[(size_t)(e0 >> 16) * 32 + lane];
                uint4 q1 = d_EWh[(size_t)(e1 >> 16) * 32 + lane];
                uint4 q2 = d_EWh[(size_t)(e2 >> 16) * 32 + lane];
                uint4 q3 = d_EWh[(size_t)(e3 >> 16) * 32 + lane];
                acc8(a, q0, __uint_as_float((unsigned)e0 << 16));
                acc8(a, q1, __uint_as_float((unsigned)e1 << 16));
                acc8(a, q2, __uint_as_float((unsigned)e2 << 16));
                acc8(a, q3, __uint_as_float((unsigned)e3 << 16));
            }
        }
        float ct = d_coef[u] + (float)dcu.y * d2;
        sv[0] += ct * fmaxf(a[0] + bq0.x, 0.f);
        sv[1] += ct * fmaxf(a[1] + bq0.y, 0.f);
        sv[2] += ct * fmaxf(a[2] + bq0.z, 0.f);
        sv[3] += ct * fmaxf(a[3] + bq0.w, 0.f);
        sv[4] += ct * fmaxf(a[4] + bq1.x, 0.f);
        sv[5] += ct * fmaxf(a[5] + bq1.y, 0.f);
        sv[6] += ct * fmaxf(a[6] + bq1.z, 0.f);
        sv[7] += ct * fmaxf(a[7] + bq1.w, 0.f);
    }
#pragma unroll
    for (int k = 0; k < 8; k++) atomicAdd(&ssv[8 * lane + k], sv[k]);
    __syncthreads();
    if (tid < 64) {
        float4 p = ((float4*)ssv)[tid];
        red4(((float4*)d_svec) + tid, p.x, p.y, p.z, p.w);
    }
}

// ---------------- K2: classifier (blocks 0..15) + state zeroing (16..99) ----
__global__ void __launch_bounds__(256) k_out(const float* __restrict__ W2,
                                             const float* __restrict__ b2,
                                             const float* __restrict__ Wc,
                                             const float* __restrict__ bc,
                                             float* __restrict__ out) {
    if (blockIdx.x < OUT_BLKS) {
        __shared__ float zb[HID];
        int t = threadIdx.x;
        if (t < HID) {
            float acc = 0.f;
            for (int k = 0; k < H2; k++) acc += d_svec[k] * W2[k * HID + t];
            zb[t] = acc * (1.0f / (float)N_POS) + b2[t];
        }
        __syncthreads();
        int c = blockIdx.x * 256 + t;
        float acc = bc[c];
#pragma unroll 8
        for (int j = 0; j < HID; j++) acc += zb[j] * Wc[j * VOCABSZ + c];
        out[c] = acc;
    } else {
        // zero per-frame state for the NEXT replay (invariant: zero on entry)
        int zt = (blockIdx.x - OUT_BLKS) * 256 + threadIdx.x;
        int nz = ZERO_BLKS * 256;
        for (int i = zt; i < N_NODES; i += nz) {
            d_dc[2 * i] = 0; d_dc[2 * i + 1] = 0;
            d_coef[i] = 0.f; d_need[i] = 0;
        }
        if (zt == 0) { d_total = 0; d_nneed = 0; }
        if (zt < 8) d_bar[zt] = 0;
    }
}

extern "C" void kernel_launch(void* const* d_in, const int* in_sizes, int n_in,
                              void* d_out, int out_size) {
    const int*   x    = (const int*)d_in[0];
    const int*   ei   = (const int*)d_in[1];
    const int*   pos  = (const int*)d_in[2];
    const float* emb  = (const float*)d_in[3];
    const float* W1   = (const float*)d_in[4];
    const float* b1   = (const float*)d_in[5];
    const float* W2   = (const float*)d_in[6];
    const float* b2   = (const float*)d_in[7];
    const float* Wc   = (const float*)d_in[8];
    const float* bc   = (const float*)d_in[9];
    float* out = (float*)d_out;
    const int* row = ei;
    const int* col = ei + N_EDGES;

    k_build<<<GRID_BUILD, 256>>>(emb, W1, row, col, pos, x);
    k_gather<<<1184, 256>>>(b1, x);
    k_out<<<OUT_BLKS + ZERO_BLKS, 256>>>(W2, b2, Wc, bc, out);
}